// round 10
// baseline (speedup 1.0000x reference)
#include <cuda_runtime.h>
#include <math.h>

#define FS     39      // total fields
#define NF     38      // fields in pairwise term (0..37)
#define NP     703     // NF*(NF-1)/2 pairs
#define NITEM  (NP*5)  // 3515 items
#define FEAT   100000
#define EMB    10
#define ROWB   (EMB*4) // 40 bytes per row
#define TPB    256
#define SLICES 2
#define IPS    1792    // items per slice (2*1792 = 3584 >= 3515)
#define KMAX   7       // IPS / TPB
#define PLO(s) ((s) * 358)   // first pair index touched by slice s
#define SPAIRN 360     // descriptors per slice (<= 359 used)
#define BATCH  2048

__device__ float g_acc[BATCH];   // zero-init; self-cleaned every launch
__device__ int   g_cnt[BATCH];   // zero-init; self-cleaned every launch

__global__ __launch_bounds__(TPB) void ffm_kernel(
    const int*   __restrict__ idxs,   // [B, FS]
    const float* __restrict__ vals,   // [B, FS]
    const float* __restrict__ emb,    // [FS, FEAT, EMB]
    const float* __restrict__ w1,     // [FEAT]
    float*       __restrict__ out)    // [B]
{
    __shared__ int   s_idx[FS];
    __shared__ float s_val[FS];
    __shared__ int4  s_pair[SPAIRN];  // descriptors for this slice's pair range
    __shared__ float s_red[TPB / 32];

    const int s = blockIdx.x;         // slice 0..1
    const int b = blockIdx.y;         // batch element
    const int t = threadIdx.x;

    if (t < FS) {
        s_idx[t] = idxs[b * FS + t];
        s_val[t] = vals[b * FS + t];
    }
    __syncthreads();

    // Prologue: build ONLY this slice's pair range [plo, plo+SPAIRN).
    // Chip-wide prologue work thus matches the unsliced kernel (R9's flaw fixed).
    const int plo = PLO(s);
    for (int q = t; q < SPAIRN; q += TPB) {
        const int p = plo + q;
        int4 d = make_int4(0, 0, 0, 0);     // zero-scale pad for p >= NP
        if (p < NP) {
            // closed-form triangular decode p -> (i, j); base(i) = i*(75-i)/2
            int i = (int)((75.0f - sqrtf(5625.0f - 8.0f * (float)p)) * 0.5f);
            if (p < i * (75 - i) / 2) --i;
            else if (p >= (i + 1) * (74 - i) / 2) ++i;
            const int base = i * (75 - i) / 2;
            const int j = p - base + i + 1;
            d.x = (i * FEAT + s_idx[j]) * ROWB;   // emb[i][idx_j] byte offset
            d.y = (j * FEAT + s_idx[i]) * ROWB;   // emb[j][idx_i] byte offset
            d.z = __float_as_int(s_val[i] * s_val[j]);
        }
        s_pair[q] = d;
    }

    float acc = 0.f, acc2 = 0.f;
    if (s == 0 && t < FS) {
        acc = w1[s_idx[t]] * s_val[t];    // first-order term (slice 0 only)
    }
    __syncthreads();

    // Main loop: this slice owns items [s*IPS, (s+1)*IPS), 7 uniform
    // items/thread, incremental (q, chunk-byte) stepping (256 = 51*5 + 1).
    const char* __restrict__ embB = (const char*)emb;
    const int item0 = s * IPS + t;
    int p0 = item0 / 5;
    int cb = (item0 - p0 * 5) * 8;
    int q  = p0 - plo;                    // relative descriptor index

    #pragma unroll
    for (int k = 0; k < KMAX; ++k) {
        const int4 d = s_pair[q];
        const float2 a = *(const float2*)(embB + (unsigned)(d.x + cb));
        const float2 v = *(const float2*)(embB + (unsigned)(d.y + cb));
        const float sc = __int_as_float(d.z);
        if (k & 1) acc2 += sc * (a.x * v.x + a.y * v.y);
        else       acc  += sc * (a.x * v.x + a.y * v.y);
        q += 51; cb += 8;
        if (cb >= ROWB) { cb -= ROWB; ++q; }
    }
    acc += acc2;

    // Block reduction.
    #pragma unroll
    for (int o = 16; o > 0; o >>= 1)
        acc += __shfl_down_sync(0xffffffffu, acc, o);
    if ((t & 31) == 0) s_red[t >> 5] = acc;
    __syncthreads();

    // Cross-slice combine: last-arriving CTA finalizes and self-cleans
    // the scratch (zeroed state restored for every graph replay).
    if (t == 0) {
        float cta = 0.f;
        #pragma unroll
        for (int w = 0; w < TPB / 32; w++) cta += s_red[w];
        atomicAdd(&g_acc[b], cta);
        __threadfence();
        const int prev = atomicAdd(&g_cnt[b], 1);
        if (prev == SLICES - 1) {
            const float tot = g_acc[b];
            out[b] = 1.f / (1.f + expf(-tot));
            g_acc[b] = 0.f;
            g_cnt[b] = 0;
        }
    }
}

extern "C" void kernel_launch(void* const* d_in, const int* in_sizes, int n_in,
                              void* d_out, int out_size) {
    const int*   idxs = (const int*)d_in[0];
    const float* vals = (const float*)d_in[1];
    const float* emb  = (const float*)d_in[2];
    const float* w1   = (const float*)d_in[3];
    float* out = (float*)d_out;

    dim3 grid(SLICES, BATCH);
    ffm_kernel<<<grid, TPB>>>(idxs, vals, emb, w1, out);
}

// round 12
// speedup vs baseline: 1.1401x; 1.1401x over previous
#include <cuda_runtime.h>
#include <math.h>

#define FS    39      // total fields
#define NF    38      // fields in pairwise term (0..37)
#define NP    703     // NF*(NF-1)/2 pairs
#define FEAT  100000
#define EMB   10
#define ROWB  (EMB*4) // 40 bytes per embedding row
#define TPB   256
#define KMAX  14      // ceil(703*5 / 256)
#define NPPAD 720     // padded pair table (max p touched = 716)

// L2 evict_last via cache-policy form (bare .L2::evict_last qualifier is
// illegal on narrow loads on sm_103; the createpolicy + .L2::cache_hint
// form is the supported encoding).
__device__ __forceinline__ unsigned long long mk_evict_last_policy() {
    unsigned long long pol;
    asm("createpolicy.fractional.L2::evict_last.b64 %0, 1.0;" : "=l"(pol));
    return pol;
}

__device__ __forceinline__ float2 ldg_el(const char* p, unsigned long long pol) {
    float2 r;
    asm("ld.global.nc.L2::cache_hint.v2.f32 {%0, %1}, [%2], %3;"
        : "=f"(r.x), "=f"(r.y) : "l"(p), "l"(pol));
    return r;
}

__global__ __launch_bounds__(TPB) void ffm_kernel(
    const int*   __restrict__ idxs,   // [B, FS]
    const float* __restrict__ vals,   // [B, FS]
    const float* __restrict__ emb,    // [FS, FEAT, EMB]
    const float* __restrict__ w1,     // [FEAT]
    float*       __restrict__ out)    // [B]
{
    __shared__ int   s_idx[FS];
    __shared__ float s_val[FS];
    __shared__ int4  s_pair[NPPAD];   // {byteOffA, byteOffB, bits(v_i*v_j), pad}
    __shared__ float s_red[TPB / 32];

    const int b = blockIdx.x;
    const int t = threadIdx.x;

    if (t < FS) {
        s_idx[t] = idxs[b * FS + t];
        s_val[t] = vals[b * FS + t];
    }
    __syncthreads();

    // Zero-scale padding so the main loop needs no bounds guard.
    for (int p = NP + t; p < NPPAD; p += TPB) {
        s_pair[p] = make_int4(0, 0, 0, 0);
    }

    // Prologue: closed-form triangular decode p -> (i, j); byte-offset
    // descriptors. base(i) = i*(75-i)/2 for NF=38.
    for (int p = t; p < NP; p += TPB) {
        int i = (int)((75.0f - sqrtf(5625.0f - 8.0f * (float)p)) * 0.5f);
        if (p < i * (75 - i) / 2) --i;
        else if (p >= (i + 1) * (74 - i) / 2) ++i;
        const int base = i * (75 - i) / 2;
        const int j = p - base + i + 1;
        int4 d;
        d.x = (i * FEAT + s_idx[j]) * ROWB;   // emb[i][idx_j] byte offset
        d.y = (j * FEAT + s_idx[i]) * ROWB;   // emb[j][idx_i] byte offset
        d.z = __float_as_int(s_val[i] * s_val[j]);
        d.w = 0;
        s_pair[p] = d;
    }

    float acc = 0.f, acc2 = 0.f;
    if (t < FS) {
        acc = w1[s_idx[t]] * s_val[t];        // first-order term
    }
    __syncthreads();

    // Main loop: uniform 14 items/thread. Per item: 1 LDS.128 + 2 LDG.64 +
    // 3 FFMA + incremental (p, chunk-byte) update (stride 256 = 51*5 + 1).
    // Gathers carry an L2 evict_last policy: touched footprint (~109MB)
    // just fits L2 (126MB), so retained lines convert the ~42% collision
    // re-touches into hits.
    const unsigned long long pol = mk_evict_last_policy();
    const char* __restrict__ embB = (const char*)emb;
    int p  = t / 5;
    int cb = (t - p * 5) * 8;

    #pragma unroll
    for (int k = 0; k < KMAX; ++k) {
        const int4 d = s_pair[p];
        const float2 a = ldg_el(embB + (unsigned)(d.x + cb), pol);
        const float2 v = ldg_el(embB + (unsigned)(d.y + cb), pol);
        const float s = __int_as_float(d.z);
        if (k & 1) acc2 += s * (a.x * v.x + a.y * v.y);
        else       acc  += s * (a.x * v.x + a.y * v.y);
        p += 51; cb += 8;
        if (cb >= ROWB) { cb -= ROWB; ++p; }
    }
    acc += acc2;

    // Block reduction.
    #pragma unroll
    for (int o = 16; o > 0; o >>= 1)
        acc += __shfl_down_sync(0xffffffffu, acc, o);
    if ((t & 31) == 0) s_red[t >> 5] = acc;
    __syncthreads();
    if (t == 0) {
        float tot = 0.f;
        #pragma unroll
        for (int w = 0; w < TPB / 32; w++) tot += s_red[w];
        out[b] = 1.f / (1.f + expf(-tot));
    }
}

extern "C" void kernel_launch(void* const* d_in, const int* in_sizes, int n_in,
                              void* d_out, int out_size) {
    const int*   idxs = (const int*)d_in[0];
    const float* vals = (const float*)d_in[1];
    const float* emb  = (const float*)d_in[2];
    const float* w1   = (const float*)d_in[3];
    float* out = (float*)d_out;

    const int batch = out_size;  // 2048
    ffm_kernel<<<batch, TPB>>>(idxs, vals, emb, w1, out);
}